// round 1
// baseline (speedup 1.0000x reference)
#include <cuda_runtime.h>
#include <cstdint>

#define L 2304
#define NBATCH 4
#define CIN 512
#define HCH 64
#define NH 8
#define DM 8

// scratch (no cudaMalloc allowed)
__device__ float g_qkv[NBATCH * 192 * L];  // [n][192][L]
__device__ float g_o[NBATCH * HCH * L];    // [n][64][L]

// ---------- packed f32x2 helpers ----------
#define PACK64(r, lo, hi) asm("mov.b64 %0, {%1,%2};" : "=l"(r) : "f"(lo), "f"(hi))
#define UNPACK64(lo, hi, r) asm("mov.b64 {%0,%1}, %2;" : "=f"(lo), "=f"(hi) : "l"(r))
#define FMA2(d, a, b, c) asm("fma.rn.f32x2 %0, %1, %2, %3;" : "=l"(d) : "l"(a), "l"(b), "l"(c))
#define MUL2(d, a, b) asm("mul.rn.f32x2 %0, %1, %2;" : "=l"(d) : "l"(a), "l"(b))

// ============================================================
// Generic tiled GEMM with bias:
//   C[n][m][l] = sum_k A[m][k] * B[n][k][l] + bias[m]
// BM=64, BN=64, BK=16; 256 threads, 4x4 microtile.
// ============================================================
__global__ void __launch_bounds__(256) gemm_bias_kernel(
    const float* __restrict__ A, const float* __restrict__ B,
    const float* __restrict__ bias, float* __restrict__ C,
    int M, int Kdim)
{
    __shared__ float As[16][65];
    __shared__ float Bs[16][68];
    int n  = blockIdx.z;
    int m0 = blockIdx.y * 64;
    int l0 = blockIdx.x * 64;
    int t  = threadIdx.x;
    int tm = t >> 4, tn = t & 15;
    const float* Bn = B + (size_t)n * Kdim * L;

    float acc[4][4];
#pragma unroll
    for (int i = 0; i < 4; i++)
#pragma unroll
        for (int j = 0; j < 4; j++) acc[i][j] = 0.f;

    for (int k0 = 0; k0 < Kdim; k0 += 16) {
        {   // A tile (transposed into smem)
            int m = t >> 2, kk = (t & 3) * 4;
            float4 a = *(const float4*)(A + (size_t)(m0 + m) * Kdim + k0 + kk);
            As[kk + 0][m] = a.x; As[kk + 1][m] = a.y;
            As[kk + 2][m] = a.z; As[kk + 3][m] = a.w;
        }
        {   // B tile
            int kk = t >> 4, nn = (t & 15) * 4;
            float4 bv = *(const float4*)(Bn + (size_t)(k0 + kk) * L + l0 + nn);
            *(float4*)&Bs[kk][nn] = bv;
        }
        __syncthreads();
#pragma unroll
        for (int kk = 0; kk < 16; kk++) {
            float ar[4], br[4];
#pragma unroll
            for (int i = 0; i < 4; i++) ar[i] = As[kk][tm * 4 + i];
#pragma unroll
            for (int j = 0; j < 4; j++) br[j] = Bs[kk][tn * 4 + j];
#pragma unroll
            for (int i = 0; i < 4; i++)
#pragma unroll
                for (int j = 0; j < 4; j++)
                    acc[i][j] = fmaf(ar[i], br[j], acc[i][j]);
        }
        __syncthreads();
    }

#pragma unroll
    for (int i = 0; i < 4; i++) {
        int m = m0 + tm * 4 + i;
        float bb = bias[m];
        float4 r = make_float4(acc[i][0] + bb, acc[i][1] + bb,
                               acc[i][2] + bb, acc[i][3] + bb);
        *(float4*)&C[((size_t)n * M + m) * L + l0 + tn * 4] = r;
    }
}

// ============================================================
// Attention: grid = 288 (4 n * 8 heads * 9 q-tiles of 256).
// Whole K,V for the head live in SMEM: row l = [k0..k7, v0..v7, pad4],
// stride 20 floats (80 B, 16B-aligned for LDS.128).
// One query per thread; single-pass softmax (no max subtraction);
// dot + accumulate use packed fma.rn.f32x2.
// ============================================================
__global__ void __launch_bounds__(256) attn_kernel()
{
    extern __shared__ float kv_s[];   // [2304][20]
    int bid = blockIdx.x;
    int qt = bid % 9;
    int nh = bid / 9;
    int h = nh % NH, n = nh / NH;
    int t = threadIdx.x;

    const float* base = g_qkv + ((size_t)n * 192 + h * 24) * L;

    // load K (c = 8+j) and V (c = 16+j) -> interleaved smem rows
#pragma unroll
    for (int j = 0; j < 16; j++) {
        const float* src = base + (size_t)(8 + j) * L;
#pragma unroll
        for (int r = 0; r < 9; r++) {
            int l = t + r * 256;
            kv_s[l * 20 + j] = src[l];
        }
    }
    __syncthreads();

    int q = qt * 256 + t;
    // q, with SCALE * log2(e) folded in
    const float QS = 0.35355339059327373f * 1.4426950408889634f;
    float qv[8];
#pragma unroll
    for (int d = 0; d < 8; d++) qv[d] = base[(size_t)d * L + q] * QS;

    unsigned long long qp[4];
#pragma unroll
    for (int j = 0; j < 4; j++) PACK64(qp[j], qv[2 * j], qv[2 * j + 1]);

    unsigned long long acc0, acc1, acc2, acc3;
    PACK64(acc0, 0.f, 0.f); PACK64(acc1, 0.f, 0.f);
    PACK64(acc2, 0.f, 0.f); PACK64(acc3, 0.f, 0.f);
    float ssum = 0.f;

    const ulonglong2* kvu = (const ulonglong2*)kv_s;   // 5 x 16B per row

#pragma unroll 4
    for (int l = 0; l < L; l++) {
        ulonglong2 kA = kvu[l * 5 + 0];   // (k0,k1),(k2,k3)
        ulonglong2 kB = kvu[l * 5 + 1];   // (k4,k5),(k6,k7)
        unsigned long long sp;
        MUL2(sp, qp[0], kA.x);
        FMA2(sp, qp[1], kA.y, sp);
        FMA2(sp, qp[2], kB.x, sp);
        FMA2(sp, qp[3], kB.y, sp);
        float slo, shi;
        UNPACK64(slo, shi, sp);
        float sarg = slo + shi;
        float e;
        asm("ex2.approx.ftz.f32 %0, %1;" : "=f"(e) : "f"(sarg));
        ssum += e;
        unsigned long long ee;
        PACK64(ee, e, e);
        ulonglong2 vA = kvu[l * 5 + 2];
        ulonglong2 vB = kvu[l * 5 + 3];
        FMA2(acc0, ee, vA.x, acc0);
        FMA2(acc1, ee, vA.y, acc1);
        FMA2(acc2, ee, vB.x, acc2);
        FMA2(acc3, ee, vB.y, acc3);
    }

    float inv = 1.0f / ssum;
    float* op = g_o + ((size_t)n * HCH + h * DM) * L + q;
    float o0, o1;
    UNPACK64(o0, o1, acc0); op[0 * L] = o0 * inv; op[1 * L] = o1 * inv;
    UNPACK64(o0, o1, acc1); op[2 * L] = o0 * inv; op[3 * L] = o1 * inv;
    UNPACK64(o0, o1, acc2); op[4 * L] = o0 * inv; op[5 * L] = o1 * inv;
    UNPACK64(o0, o1, acc3); op[6 * L] = o0 * inv; op[7 * L] = o1 * inv;
}

// ============================================================
// Pos 3x3 conv on V (64->64, SAME), accumulated into g_o.
// grid = (9 tiles of 16x16, 4 oc-groups of 16, 4 n), 256 threads.
// ============================================================
__global__ void __launch_bounds__(256) pos_conv_kernel(
    const float* __restrict__ pw, const float* __restrict__ pb)
{
    __shared__ float in_s[16][18][18];
    __shared__ float w_s[16][9][16];
    int n    = blockIdx.z;
    int ocg  = blockIdx.y;
    int tile = blockIdx.x;
    int y0 = (tile / 3) * 16, x0 = (tile % 3) * 16;
    int t = threadIdx.x;
    int ty = t / 16, tx = t % 16;

    float acc[16];
#pragma unroll
    for (int oc = 0; oc < 16; oc++) acc[oc] = 0.f;

    for (int icc = 0; icc < 4; icc++) {
        int ic0 = icc * 16;
        __syncthreads();
        for (int idx = t; idx < 16 * 18 * 18; idx += 256) {
            int ic = idx / 324, r = idx % 324, yy = r / 18, xx = r % 18;
            int gy = y0 + yy - 1, gx = x0 + xx - 1;
            float v = 0.f;
            if (gy >= 0 && gy < 48 && gx >= 0 && gx < 48) {
                int icg = ic0 + ic;
                int c = (icg >> 3) * 24 + 16 + (icg & 7);   // v channel in qkv
                v = g_qkv[((size_t)n * 192 + c) * L + gy * 48 + gx];
            }
            in_s[ic][yy][xx] = v;
        }
        for (int idx = t; idx < 2304; idx += 256) {
            int oc = idx / 144, r = idx % 144, ic = r / 9, tap = r % 9;
            w_s[ic][tap][oc] = pw[((size_t)(ocg * 16 + oc) * 64 + ic0 + ic) * 9 + tap];
        }
        __syncthreads();
#pragma unroll 1
        for (int ic = 0; ic < 16; ic++) {
#pragma unroll
            for (int tap = 0; tap < 9; tap++) {
                int dy = tap / 3, dx = tap % 3;
                float iv = in_s[ic][ty + dy][tx + dx];
#pragma unroll
                for (int oc = 0; oc < 16; oc++)
                    acc[oc] = fmaf(iv, w_s[ic][tap][oc], acc[oc]);
            }
        }
    }

    int px = (y0 + ty) * 48 + x0 + tx;
#pragma unroll
    for (int oc = 0; oc < 16; oc++) {
        int c = ocg * 16 + oc;
        size_t off = ((size_t)n * HCH + c) * L + px;
        g_o[off] += acc[oc] + pb[c];
    }
}

// ============================================================
extern "C" void kernel_launch(void* const* d_in, const int* in_sizes, int n_in,
                              void* d_out, int out_size)
{
    const float* x     = (const float*)d_in[0];
    const float* qkv_w = (const float*)d_in[1];
    const float* qkv_b = (const float*)d_in[2];
    const float* pos_w = (const float*)d_in[3];
    const float* pos_b = (const float*)d_in[4];
    const float* res_w = (const float*)d_in[5];
    const float* res_b = (const float*)d_in[6];
    float* out = (float*)d_out;

    float* qkv_ptr = nullptr;
    float* o_ptr   = nullptr;
    cudaGetSymbolAddress((void**)&qkv_ptr, g_qkv);
    cudaGetSymbolAddress((void**)&o_ptr, g_o);

    // K1: qkv 1x1 conv as GEMM  [192 x 512] * [512 x 2304] per batch
    gemm_bias_kernel<<<dim3(36, 3, NBATCH), 256>>>(qkv_w, x, qkv_b, qkv_ptr, 192, CIN);

    // K2: attention
    const int ATTN_SMEM = L * 20 * 4;  // 184320 B
    cudaFuncSetAttribute(attn_kernel, cudaFuncAttributeMaxDynamicSharedMemorySize, ATTN_SMEM);
    attn_kernel<<<288, 256, ATTN_SMEM>>>();

    // K3: pos conv, accumulate into g_o
    pos_conv_kernel<<<dim3(9, 4, NBATCH), 256>>>(pos_w, pos_b);

    // K4: res 1x1 conv as GEMM  [512 x 64] * [64 x 2304] per batch
    gemm_bias_kernel<<<dim3(36, 8, NBATCH), 256>>>(res_w, o_ptr, res_b, out, 512, HCH);
}

// round 2
// speedup vs baseline: 1.0132x; 1.0132x over previous
#include <cuda_runtime.h>
#include <cstdint>

#define L 2304
#define NBATCH 4
#define CIN 512
#define HCH 64
#define NH 8
#define DM 8

#define NSEG 4
#define SEGK (L / NSEG)      // 576 keys per segment
#define NQ (NBATCH * NH * L) // 73728 total queries

// scratch (no cudaMalloc allowed)
__device__ float g_qkv[NBATCH * 192 * L];   // [n][192][L]
__device__ float g_o[NBATCH * HCH * L];     // [n][64][L]
__device__ float g_psum[NSEG * NQ];         // partial exp-sums
__device__ float g_pacc[NSEG * DM * NQ];    // partial V-accumulators

// ---------- packed f32x2 helpers ----------
#define PACK64(r, lo, hi) asm("mov.b64 %0, {%1,%2};" : "=l"(r) : "f"(lo), "f"(hi))
#define UNPACK64(lo, hi, r) asm("mov.b64 {%0,%1}, %2;" : "=f"(lo), "=f"(hi) : "l"(r))
#define FMA2(d, a, b, c) asm("fma.rn.f32x2 %0, %1, %2, %3;" : "=l"(d) : "l"(a), "l"(b), "l"(c))
#define MUL2(d, a, b) asm("mul.rn.f32x2 %0, %1, %2;" : "=l"(d) : "l"(a), "l"(b))

// ============================================================
// Tiled GEMM with bias: C[n][m][l] = sum_k A[m][k]*B[n][k][l] + bias[m]
// BM=64, BN=64, BK=16; 256 threads, 4x4 microtile, LDS.128 smem reads.
// ============================================================
__global__ void __launch_bounds__(256) gemm_bias_kernel(
    const float* __restrict__ A, const float* __restrict__ B,
    const float* __restrict__ bias, float* __restrict__ C,
    int M, int Kdim)
{
    __shared__ float As[16][68];
    __shared__ float Bs[16][68];
    int n  = blockIdx.z;
    int m0 = blockIdx.y * 64;
    int l0 = blockIdx.x * 64;
    int t  = threadIdx.x;
    int tm = t >> 4, tn = t & 15;
    const float* Bn = B + (size_t)n * Kdim * L;

    float acc[4][4];
#pragma unroll
    for (int i = 0; i < 4; i++)
#pragma unroll
        for (int j = 0; j < 4; j++) acc[i][j] = 0.f;

    for (int k0 = 0; k0 < Kdim; k0 += 16) {
        {   // A tile (transposed into smem)
            int m = t >> 2, kk = (t & 3) * 4;
            float4 a = *(const float4*)(A + (size_t)(m0 + m) * Kdim + k0 + kk);
            As[kk + 0][m] = a.x; As[kk + 1][m] = a.y;
            As[kk + 2][m] = a.z; As[kk + 3][m] = a.w;
        }
        {   // B tile
            int kk = t >> 4, nn = (t & 15) * 4;
            float4 bv = *(const float4*)(Bn + (size_t)(k0 + kk) * L + l0 + nn);
            *(float4*)&Bs[kk][nn] = bv;
        }
        __syncthreads();
#pragma unroll
        for (int kk = 0; kk < 16; kk++) {
            float4 a4 = *(const float4*)&As[kk][tm * 4];
            float4 b4 = *(const float4*)&Bs[kk][tn * 4];
            float ar[4] = {a4.x, a4.y, a4.z, a4.w};
            float br[4] = {b4.x, b4.y, b4.z, b4.w};
#pragma unroll
            for (int i = 0; i < 4; i++)
#pragma unroll
                for (int j = 0; j < 4; j++)
                    acc[i][j] = fmaf(ar[i], br[j], acc[i][j]);
        }
        __syncthreads();
    }

#pragma unroll
    for (int i = 0; i < 4; i++) {
        int m = m0 + tm * 4 + i;
        float bb = bias[m];
        float4 r = make_float4(acc[i][0] + bb, acc[i][1] + bb,
                               acc[i][2] + bb, acc[i][3] + bb);
        *(float4*)&C[((size_t)n * M + m) * L + l0 + tn * 4] = r;
    }
}

// ============================================================
// Attention partial: grid = 1152 (4 n * 8 h * 9 q-tiles * 4 key-segments).
// Segment's K,V (576 rows) in SMEM: row = [k0..k7, v0..v7, pad4] (80B).
// One query per thread; single-pass softmax without max subtraction
// (logits bounded ~|8|, exp stays finite in fp32 -> exact same math).
// 46 KB smem -> 4 CTAs/SM -> 100% occupancy.
// ============================================================
__global__ void __launch_bounds__(256, 4) attn_part_kernel()
{
    extern __shared__ float kv_s[];   // [576][20]
    int bid = blockIdx.x;
    int seg = bid & 3;
    int qt  = (bid >> 2) % 9;
    int nh  = bid / 36;
    int h = nh % NH, n = nh / NH;
    int t = threadIdx.x;

    const float* base = g_qkv + ((size_t)n * 192 + h * 24) * L;
    int l0 = seg * SEGK;

    // load K (c=8+j) and V (c=16+j) rows [l0, l0+576) -> interleaved smem
#pragma unroll
    for (int j = 0; j < 16; j++) {
        const float* src = base + (size_t)(8 + j) * L + l0;
        for (int idx = t; idx < SEGK; idx += 256)
            kv_s[idx * 20 + j] = src[idx];
    }
    __syncthreads();

    int q = qt * 256 + t;
    const float QS = 0.35355339059327373f * 1.4426950408889634f; // SCALE*log2(e)
    float qv[8];
#pragma unroll
    for (int d = 0; d < 8; d++) qv[d] = base[(size_t)d * L + q] * QS;

    unsigned long long qp[4];
#pragma unroll
    for (int j = 0; j < 4; j++) PACK64(qp[j], qv[2 * j], qv[2 * j + 1]);

    unsigned long long acc0, acc1, acc2, acc3;
    PACK64(acc0, 0.f, 0.f); PACK64(acc1, 0.f, 0.f);
    PACK64(acc2, 0.f, 0.f); PACK64(acc3, 0.f, 0.f);
    float ssum = 0.f;

    const ulonglong2* kvu = (const ulonglong2*)kv_s;   // 5 x 16B per row

#pragma unroll 4
    for (int l = 0; l < SEGK; l++) {
        ulonglong2 kA = kvu[l * 5 + 0];
        ulonglong2 kB = kvu[l * 5 + 1];
        unsigned long long sp;
        MUL2(sp, qp[0], kA.x);
        FMA2(sp, qp[1], kA.y, sp);
        FMA2(sp, qp[2], kB.x, sp);
        FMA2(sp, qp[3], kB.y, sp);
        float slo, shi;
        UNPACK64(slo, shi, sp);
        float sarg = slo + shi;
        float e;
        asm("ex2.approx.ftz.f32 %0, %1;" : "=f"(e) : "f"(sarg));
        ssum += e;
        unsigned long long ee;
        PACK64(ee, e, e);
        ulonglong2 vA = kvu[l * 5 + 2];
        ulonglong2 vB = kvu[l * 5 + 3];
        FMA2(acc0, ee, vA.x, acc0);
        FMA2(acc1, ee, vA.y, acc1);
        FMA2(acc2, ee, vB.x, acc2);
        FMA2(acc3, ee, vB.y, acc3);
    }

    // partials out (coalesced per (seg,d) plane)
    int gq = nh * L + q;
    g_psum[seg * NQ + gq] = ssum;
    float o0, o1;
    UNPACK64(o0, o1, acc0);
    g_pacc[(seg * 8 + 0) * NQ + gq] = o0; g_pacc[(seg * 8 + 1) * NQ + gq] = o1;
    UNPACK64(o0, o1, acc1);
    g_pacc[(seg * 8 + 2) * NQ + gq] = o0; g_pacc[(seg * 8 + 3) * NQ + gq] = o1;
    UNPACK64(o0, o1, acc2);
    g_pacc[(seg * 8 + 4) * NQ + gq] = o0; g_pacc[(seg * 8 + 5) * NQ + gq] = o1;
    UNPACK64(o0, o1, acc3);
    g_pacc[(seg * 8 + 6) * NQ + gq] = o0; g_pacc[(seg * 8 + 7) * NQ + gq] = o1;
}

// ============================================================
// Combine partials: o[d] = (sum_seg acc)/ (sum_seg ssum), write to g_o.
// ============================================================
__global__ void __launch_bounds__(256) attn_combine_kernel()
{
    int gq = blockIdx.x * 256 + threadIdx.x;
    float s = 0.f;
#pragma unroll
    for (int seg = 0; seg < NSEG; seg++) s += g_psum[seg * NQ + gq];
    float inv = 1.0f / s;
    int nh = gq / L;
    int q  = gq - nh * L;
    float* op = g_o + ((size_t)nh * 8) * L + q;
#pragma unroll
    for (int d = 0; d < 8; d++) {
        float o = 0.f;
#pragma unroll
        for (int seg = 0; seg < NSEG; seg++) o += g_pacc[(seg * 8 + d) * NQ + gq];
        op[(size_t)d * L] = o * inv;
    }
}

// ============================================================
// Pos 3x3 conv on V (64->64, SAME), accumulated into g_o.
// ============================================================
__global__ void __launch_bounds__(256) pos_conv_kernel(
    const float* __restrict__ pw, const float* __restrict__ pb)
{
    __shared__ float in_s[16][18][18];
    __shared__ float w_s[16][9][16];
    int n    = blockIdx.z;
    int ocg  = blockIdx.y;
    int tile = blockIdx.x;
    int y0 = (tile / 3) * 16, x0 = (tile % 3) * 16;
    int t = threadIdx.x;
    int ty = t / 16, tx = t % 16;

    float acc[16];
#pragma unroll
    for (int oc = 0; oc < 16; oc++) acc[oc] = 0.f;

    for (int icc = 0; icc < 4; icc++) {
        int ic0 = icc * 16;
        __syncthreads();
        for (int idx = t; idx < 16 * 18 * 18; idx += 256) {
            int ic = idx / 324, r = idx % 324, yy = r / 18, xx = r % 18;
            int gy = y0 + yy - 1, gx = x0 + xx - 1;
            float v = 0.f;
            if (gy >= 0 && gy < 48 && gx >= 0 && gx < 48) {
                int icg = ic0 + ic;
                int c = (icg >> 3) * 24 + 16 + (icg & 7);   // v channel in qkv
                v = g_qkv[((size_t)n * 192 + c) * L + gy * 48 + gx];
            }
            in_s[ic][yy][xx] = v;
        }
        for (int idx = t; idx < 2304; idx += 256) {
            int oc = idx / 144, r = idx % 144, ic = r / 9, tap = r % 9;
            w_s[ic][tap][oc] = pw[((size_t)(ocg * 16 + oc) * 64 + ic0 + ic) * 9 + tap];
        }
        __syncthreads();
#pragma unroll 1
        for (int ic = 0; ic < 16; ic++) {
#pragma unroll
            for (int tap = 0; tap < 9; tap++) {
                int dy = tap / 3, dx = tap % 3;
                float iv = in_s[ic][ty + dy][tx + dx];
#pragma unroll
                for (int oc = 0; oc < 16; oc++)
                    acc[oc] = fmaf(iv, w_s[ic][tap][oc], acc[oc]);
            }
        }
    }

    int px = (y0 + ty) * 48 + x0 + tx;
#pragma unroll
    for (int oc = 0; oc < 16; oc++) {
        int c = ocg * 16 + oc;
        size_t off = ((size_t)n * HCH + c) * L + px;
        g_o[off] += acc[oc] + pb[c];
    }
}

// ============================================================
extern "C" void kernel_launch(void* const* d_in, const int* in_sizes, int n_in,
                              void* d_out, int out_size)
{
    const float* x     = (const float*)d_in[0];
    const float* qkv_w = (const float*)d_in[1];
    const float* qkv_b = (const float*)d_in[2];
    const float* pos_w = (const float*)d_in[3];
    const float* pos_b = (const float*)d_in[4];
    const float* res_w = (const float*)d_in[5];
    const float* res_b = (const float*)d_in[6];
    float* out = (float*)d_out;

    float* qkv_ptr = nullptr;
    float* o_ptr   = nullptr;
    cudaGetSymbolAddress((void**)&qkv_ptr, g_qkv);
    cudaGetSymbolAddress((void**)&o_ptr, g_o);

    // K1: qkv 1x1 conv as GEMM  [192 x 512] * [512 x 2304] per batch
    gemm_bias_kernel<<<dim3(36, 3, NBATCH), 256>>>(qkv_w, x, qkv_b, qkv_ptr, 192, CIN);

    // K2: attention partials (4 key-segments -> 4 CTAs/SM)
    const int ATTN_SMEM = SEGK * 20 * 4;  // 46080 B
    attn_part_kernel<<<NBATCH * NH * 9 * NSEG, 256, ATTN_SMEM>>>();

    // K3: combine + normalize
    attn_combine_kernel<<<NQ / 256, 256>>>();

    // K4: pos conv, accumulate into g_o
    pos_conv_kernel<<<dim3(9, 4, NBATCH), 256>>>(pos_w, pos_b);

    // K5: res 1x1 conv as GEMM  [512 x 64] * [64 x 2304] per batch
    gemm_bias_kernel<<<dim3(36, 8, NBATCH), 256>>>(res_w, o_ptr, res_b, out, 512, HCH);
}

// round 3
// speedup vs baseline: 1.1636x; 1.1483x over previous
#include <cuda_runtime.h>
#include <cstdint>

#define L 2304
#define NBATCH 4
#define CIN 512
#define HCH 64
#define NH 8
#define DM 8

#define NSEG 4
#define SEGK (L / NSEG)      // 576 keys per segment
#define NQ (NBATCH * NH * L) // 73728 total queries

// scratch (no cudaMalloc allowed)
__device__ float g_qkv[NBATCH * 192 * L];   // [n][192][L]
__device__ float g_o[NBATCH * HCH * L];     // [n][64][L]
__device__ float g_psum[NSEG * NQ];         // partial exp-sums
__device__ float g_pacc[NSEG * DM * NQ];    // partial V-accumulators

// ---------- packed f32x2 helpers ----------
#define PACK64(r, lo, hi) asm("mov.b64 %0, {%1,%2};" : "=l"(r) : "f"(lo), "f"(hi))
#define UNPACK64(lo, hi, r) asm("mov.b64 {%0,%1}, %2;" : "=f"(lo), "=f"(hi) : "l"(r))
#define FMA2(d, a, b, c) asm("fma.rn.f32x2 %0, %1, %2, %3;" : "=l"(d) : "l"(a), "l"(b), "l"(c))
#define MUL2(d, a, b) asm("mul.rn.f32x2 %0, %1, %2;" : "=l"(d) : "l"(a), "l"(b))

// ============================================================
// Tiled GEMM with bias: C[n][m][l] = sum_k A[m][k]*B[n][k][l] + bias[m]
// BM=64, BN=128, BK=16; 256 threads, 4x8 microtile in two column
// groups (tn*4 and 64+tn*4) so every LDS is a conflict-free LDS.128.
// ============================================================
__global__ void __launch_bounds__(256) gemm_bias_kernel(
    const float* __restrict__ A, const float* __restrict__ B,
    const float* __restrict__ bias, float* __restrict__ C,
    int M, int Kdim)
{
    __shared__ float As[16][68];
    __shared__ float Bs[16][132];
    int n  = blockIdx.z;
    int m0 = blockIdx.y * 64;
    int l0 = blockIdx.x * 128;
    int t  = threadIdx.x;
    int tm = t >> 4, tn = t & 15;
    const float* Bn = B + (size_t)n * Kdim * L;

    float acc[4][8];
#pragma unroll
    for (int i = 0; i < 4; i++)
#pragma unroll
        for (int j = 0; j < 8; j++) acc[i][j] = 0.f;

    for (int k0 = 0; k0 < Kdim; k0 += 16) {
        {   // A tile (transposed into smem)
            int m = t >> 2, kk = (t & 3) * 4;
            float4 a = *(const float4*)(A + (size_t)(m0 + m) * Kdim + k0 + kk);
            As[kk + 0][m] = a.x; As[kk + 1][m] = a.y;
            As[kk + 2][m] = a.z; As[kk + 3][m] = a.w;
        }
        {   // B tile: two column groups per thread
            int kk = t >> 4;
            const float* src = Bn + (size_t)(k0 + kk) * L + l0;
            float4 b0 = *(const float4*)(src + tn * 4);
            float4 b1 = *(const float4*)(src + 64 + tn * 4);
            *(float4*)&Bs[kk][tn * 4] = b0;
            *(float4*)&Bs[kk][64 + tn * 4] = b1;
        }
        __syncthreads();
#pragma unroll
        for (int kk = 0; kk < 16; kk++) {
            float4 a4 = *(const float4*)&As[kk][tm * 4];
            float4 b0 = *(const float4*)&Bs[kk][tn * 4];
            float4 b1 = *(const float4*)&Bs[kk][64 + tn * 4];
            float ar[4] = {a4.x, a4.y, a4.z, a4.w};
            float br[8] = {b0.x, b0.y, b0.z, b0.w, b1.x, b1.y, b1.z, b1.w};
#pragma unroll
            for (int i = 0; i < 4; i++)
#pragma unroll
                for (int j = 0; j < 8; j++)
                    acc[i][j] = fmaf(ar[i], br[j], acc[i][j]);
        }
        __syncthreads();
    }

#pragma unroll
    for (int i = 0; i < 4; i++) {
        int m = m0 + tm * 4 + i;
        float bb = bias[m];
        float* dst = C + ((size_t)n * M + m) * L + l0;
        float4 r0 = make_float4(acc[i][0] + bb, acc[i][1] + bb,
                                acc[i][2] + bb, acc[i][3] + bb);
        float4 r1 = make_float4(acc[i][4] + bb, acc[i][5] + bb,
                                acc[i][6] + bb, acc[i][7] + bb);
        *(float4*)(dst + tn * 4) = r0;
        *(float4*)(dst + 64 + tn * 4) = r1;
    }
}

// ============================================================
// Attention partial: grid = 512 (4 n * 8 h * 4 q-tiles(576) * 4 segs).
// 288 threads, 2 queries/thread (q0 = jt*576+t, q1 = q0+288).
// Segment KV in SMEM: row = [k0..k7, v0..v7, pad4] (80B, LDS.128).
// Single-pass softmax without max subtraction (logits bounded ~|8|).
// ============================================================
__global__ void __launch_bounds__(288, 3) attn_part_kernel()
{
    extern __shared__ float kv_s[];   // [576][20]
    int bid = blockIdx.x;
    int seg = bid & 3;
    int jt  = (bid >> 2) & 3;
    int nh  = bid >> 4;
    int h = nh & 7, n = nh >> 3;
    int t = threadIdx.x;

    const float* base = g_qkv + ((size_t)n * 192 + h * 24) * L;
    int l0 = seg * SEGK;

    // load K (c=8+j) and V (c=16+j) rows [l0, l0+576)
#pragma unroll
    for (int j = 0; j < 16; j++) {
        const float* src = base + (size_t)(8 + j) * L + l0;
        kv_s[t * 20 + j]         = src[t];
        kv_s[(t + 288) * 20 + j] = src[t + 288];
    }
    __syncthreads();

    int q0 = jt * 576 + t;
    int q1 = q0 + 288;
    const float QS = 0.35355339059327373f * 1.4426950408889634f; // SCALE*log2(e)

    unsigned long long qpA[4], qpB[4];
#pragma unroll
    for (int j = 0; j < 4; j++) {
        float a0 = base[(size_t)(2 * j) * L + q0] * QS;
        float a1 = base[(size_t)(2 * j + 1) * L + q0] * QS;
        PACK64(qpA[j], a0, a1);
        float b0 = base[(size_t)(2 * j) * L + q1] * QS;
        float b1 = base[(size_t)(2 * j + 1) * L + q1] * QS;
        PACK64(qpB[j], b0, b1);
    }

    unsigned long long accA[4], accB[4];
#pragma unroll
    for (int j = 0; j < 4; j++) { PACK64(accA[j], 0.f, 0.f); PACK64(accB[j], 0.f, 0.f); }
    float ssA = 0.f, ssB = 0.f;

    const ulonglong2* kvu = (const ulonglong2*)kv_s;   // 5 x 16B per row

#pragma unroll 4
    for (int l = 0; l < SEGK; l++) {
        ulonglong2 kA = kvu[l * 5 + 0];
        ulonglong2 kB = kvu[l * 5 + 1];
        unsigned long long s0, s1;
        MUL2(s0, qpA[0], kA.x);
        MUL2(s1, qpB[0], kA.x);
        FMA2(s0, qpA[1], kA.y, s0);
        FMA2(s1, qpB[1], kA.y, s1);
        FMA2(s0, qpA[2], kB.x, s0);
        FMA2(s1, qpB[2], kB.x, s1);
        FMA2(s0, qpA[3], kB.y, s0);
        FMA2(s1, qpB[3], kB.y, s1);
        float lo, hi, e0, e1;
        UNPACK64(lo, hi, s0);
        float g0 = lo + hi;
        UNPACK64(lo, hi, s1);
        float g1 = lo + hi;
        asm("ex2.approx.ftz.f32 %0, %1;" : "=f"(e0) : "f"(g0));
        asm("ex2.approx.ftz.f32 %0, %1;" : "=f"(e1) : "f"(g1));
        ssA += e0;
        ssB += e1;
        unsigned long long ee0, ee1;
        PACK64(ee0, e0, e0);
        PACK64(ee1, e1, e1);
        ulonglong2 vA = kvu[l * 5 + 2];
        ulonglong2 vB = kvu[l * 5 + 3];
        FMA2(accA[0], ee0, vA.x, accA[0]);
        FMA2(accB[0], ee1, vA.x, accB[0]);
        FMA2(accA[1], ee0, vA.y, accA[1]);
        FMA2(accB[1], ee1, vA.y, accB[1]);
        FMA2(accA[2], ee0, vB.x, accA[2]);
        FMA2(accB[2], ee1, vB.x, accB[2]);
        FMA2(accA[3], ee0, vB.y, accA[3]);
        FMA2(accB[3], ee1, vB.y, accB[3]);
    }

    int gq0 = nh * L + q0;
    int gq1 = nh * L + q1;
    g_psum[seg * NQ + gq0] = ssA;
    g_psum[seg * NQ + gq1] = ssB;
    float o0, o1;
#pragma unroll
    for (int j = 0; j < 4; j++) {
        UNPACK64(o0, o1, accA[j]);
        g_pacc[(seg * 8 + 2 * j) * NQ + gq0] = o0;
        g_pacc[(seg * 8 + 2 * j + 1) * NQ + gq0] = o1;
        UNPACK64(o0, o1, accB[j]);
        g_pacc[(seg * 8 + 2 * j) * NQ + gq1] = o0;
        g_pacc[(seg * 8 + 2 * j + 1) * NQ + gq1] = o1;
    }
}

// ============================================================
// Combine partials: o[d] = (sum_seg acc)/(sum_seg ssum) -> g_o.
// ============================================================
__global__ void __launch_bounds__(256) attn_combine_kernel()
{
    int gq = blockIdx.x * 256 + threadIdx.x;
    float s = 0.f;
#pragma unroll
    for (int seg = 0; seg < NSEG; seg++) s += g_psum[seg * NQ + gq];
    float inv = 1.0f / s;
    int nh = gq / L;
    int q  = gq - nh * L;
    float* op = g_o + ((size_t)nh * 8) * L + q;
#pragma unroll
    for (int d = 0; d < 8; d++) {
        float o = 0.f;
#pragma unroll
        for (int seg = 0; seg < NSEG; seg++) o += g_pacc[(seg * 8 + d) * NQ + gq];
        op[(size_t)d * L] = o * inv;
    }
}

// ============================================================
// Pos 3x3 conv as implicit GEMM over V:
//   g_o[n][oc][px] += sum_{ic,tap} pw[oc][ic*9+tap] * V[n][ic][shift(px,tap)]
// BM=64 (all oc), BN=32 px, K=576; grid = (72, 1, 4) = 288 CTAs.
// ============================================================
__global__ void __launch_bounds__(256) pos_gemm_kernel(
    const float* __restrict__ pw, const float* __restrict__ pb)
{
    __shared__ float As[16][68];
    __shared__ float Bs[16][36];
    int n  = blockIdx.z;
    int l0 = blockIdx.x * 32;
    int t  = threadIdx.x;
    int tm = t >> 4, tn = t & 15;

    float acc[4][2];
#pragma unroll
    for (int i = 0; i < 4; i++) { acc[i][0] = 0.f; acc[i][1] = 0.f; }

    for (int k0 = 0; k0 < 576; k0 += 16) {
        {   // A = pos weights [64 oc][576], transposed tile
            int m = t >> 2, kk = (t & 3) * 4;
            float4 a = *(const float4*)(pw + (size_t)m * 576 + k0 + kk);
            As[kk + 0][m] = a.x; As[kk + 1][m] = a.y;
            As[kk + 2][m] = a.z; As[kk + 3][m] = a.w;
        }
        {   // B = implicit im2col gather of V (2 elements per thread)
#pragma unroll
            for (int u = 0; u < 2; u++) {
                int e = t * 2 + u;
                int kk = e >> 5, col = e & 31;
                int k = k0 + kk;
                int ic = k / 9;
                int tap = k - ic * 9;
                int dy = tap / 3 - 1, dx = tap - (tap / 3) * 3 - 1;
                int px = l0 + col;
                int y = px / 48, x = px - y * 48;
                int gy = y + dy, gx = x + dx;
                float v = 0.f;
                if ((unsigned)gy < 48u && (unsigned)gx < 48u) {
                    int c = (ic >> 3) * 24 + 16 + (ic & 7);   // v channel in qkv
                    v = g_qkv[((size_t)n * 192 + c) * L + gy * 48 + gx];
                }
                Bs[kk][col] = v;
            }
        }
        __syncthreads();
#pragma unroll
        for (int kk = 0; kk < 16; kk++) {
            float4 a4 = *(const float4*)&As[kk][tm * 4];
            float2 b2 = *(const float2*)&Bs[kk][tn * 2];
            float ar[4] = {a4.x, a4.y, a4.z, a4.w};
#pragma unroll
            for (int i = 0; i < 4; i++) {
                acc[i][0] = fmaf(ar[i], b2.x, acc[i][0]);
                acc[i][1] = fmaf(ar[i], b2.y, acc[i][1]);
            }
        }
        __syncthreads();
    }

#pragma unroll
    for (int i = 0; i < 4; i++) {
        int m = tm * 4 + i;
        float bb = pb[m];
        size_t off = ((size_t)n * HCH + m) * L + l0 + tn * 2;
        g_o[off]     += acc[i][0] + bb;
        g_o[off + 1] += acc[i][1] + bb;
    }
}

// ============================================================
extern "C" void kernel_launch(void* const* d_in, const int* in_sizes, int n_in,
                              void* d_out, int out_size)
{
    const float* x     = (const float*)d_in[0];
    const float* qkv_w = (const float*)d_in[1];
    const float* qkv_b = (const float*)d_in[2];
    const float* pos_w = (const float*)d_in[3];
    const float* pos_b = (const float*)d_in[4];
    const float* res_w = (const float*)d_in[5];
    const float* res_b = (const float*)d_in[6];
    float* out = (float*)d_out;

    float* qkv_ptr = nullptr;
    float* o_ptr   = nullptr;
    cudaGetSymbolAddress((void**)&qkv_ptr, g_qkv);
    cudaGetSymbolAddress((void**)&o_ptr, g_o);

    // K1: qkv 1x1 conv as GEMM  [192 x 512] * [512 x 2304] per batch
    gemm_bias_kernel<<<dim3(18, 3, NBATCH), 256>>>(qkv_w, x, qkv_b, qkv_ptr, 192, CIN);

    // K2: attention partials (2 queries/thread, 288 threads, 4 segments)
    const int ATTN_SMEM = SEGK * 20 * 4;  // 46080 B
    attn_part_kernel<<<NBATCH * NH * 4 * NSEG, 288, ATTN_SMEM>>>();

    // K3: combine + normalize
    attn_combine_kernel<<<NQ / 256, 256>>>();

    // K4: pos conv as implicit GEMM, accumulate into g_o
    pos_gemm_kernel<<<dim3(72, 1, NBATCH), 256>>>(pos_w, pos_b);

    // K5: res 1x1 conv as GEMM  [512 x 64] * [64 x 2304] per batch
    gemm_bias_kernel<<<dim3(18, 8, NBATCH), 256>>>(res_w, o_ptr, res_b, out, 512, HCH);
}

// round 4
// speedup vs baseline: 1.1744x; 1.0093x over previous
#include <cuda_runtime.h>
#include <cstdint>

#define L 2304
#define NBATCH 4
#define CIN 512
#define HCH 64
#define NH 8
#define DM 8

#define NSEG 4
#define SEGK (L / NSEG)      // 576 keys per segment -> 288 key-pairs
#define NPAIR (SEGK / 2)
#define NQ (NBATCH * NH * L) // 73728 total queries

// scratch (no cudaMalloc allowed)
__device__ float g_qkv[NBATCH * 192 * L];   // [n][192][L]
__device__ float g_o[NBATCH * HCH * L];     // [n][64][L]
__device__ float g_psum[NSEG * NQ];         // partial exp-sums
__device__ float g_pacc[NSEG * DM * NQ];    // partial V-accumulators

// ---------- packed f32x2 helpers ----------
#define PACK64(r, lo, hi) asm("mov.b64 %0, {%1,%2};" : "=l"(r) : "f"(lo), "f"(hi))
#define UNPACK64(lo, hi, r) asm("mov.b64 {%0,%1}, %2;" : "=f"(lo), "=f"(hi) : "l"(r))
#define FMA2(d, a, b, c) asm("fma.rn.f32x2 %0, %1, %2, %3;" : "=l"(d) : "l"(a), "l"(b), "l"(c))
#define MUL2(d, a, b) asm("mul.rn.f32x2 %0, %1, %2;" : "=l"(d) : "l"(a), "l"(b))
#define ADD2(d, a, b) asm("add.rn.f32x2 %0, %1, %2;" : "=l"(d) : "l"(a), "l"(b))

// ============================================================
// Tiled GEMM with bias: C[n][m][l] = sum_k A[m][k]*B[n][k][l] + bias[m]
// BM=64, BN=128, BK=16; 256 threads, 4x8 microtile.
// ============================================================
__global__ void __launch_bounds__(256) gemm_bias_kernel(
    const float* __restrict__ A, const float* __restrict__ B,
    const float* __restrict__ bias, float* __restrict__ C,
    int M, int Kdim)
{
    __shared__ float As[16][68];
    __shared__ float Bs[16][132];
    int n  = blockIdx.z;
    int m0 = blockIdx.y * 64;
    int l0 = blockIdx.x * 128;
    int t  = threadIdx.x;
    int tm = t >> 4, tn = t & 15;
    const float* Bn = B + (size_t)n * Kdim * L;

    float acc[4][8];
#pragma unroll
    for (int i = 0; i < 4; i++)
#pragma unroll
        for (int j = 0; j < 8; j++) acc[i][j] = 0.f;

    for (int k0 = 0; k0 < Kdim; k0 += 16) {
        {
            int m = t >> 2, kk = (t & 3) * 4;
            float4 a = *(const float4*)(A + (size_t)(m0 + m) * Kdim + k0 + kk);
            As[kk + 0][m] = a.x; As[kk + 1][m] = a.y;
            As[kk + 2][m] = a.z; As[kk + 3][m] = a.w;
        }
        {
            int kk = t >> 4;
            const float* src = Bn + (size_t)(k0 + kk) * L + l0;
            float4 b0 = *(const float4*)(src + tn * 4);
            float4 b1 = *(const float4*)(src + 64 + tn * 4);
            *(float4*)&Bs[kk][tn * 4] = b0;
            *(float4*)&Bs[kk][64 + tn * 4] = b1;
        }
        __syncthreads();
#pragma unroll
        for (int kk = 0; kk < 16; kk++) {
            float4 a4 = *(const float4*)&As[kk][tm * 4];
            float4 b0 = *(const float4*)&Bs[kk][tn * 4];
            float4 b1 = *(const float4*)&Bs[kk][64 + tn * 4];
            float ar[4] = {a4.x, a4.y, a4.z, a4.w};
            float br[8] = {b0.x, b0.y, b0.z, b0.w, b1.x, b1.y, b1.z, b1.w};
#pragma unroll
            for (int i = 0; i < 4; i++)
#pragma unroll
                for (int j = 0; j < 8; j++)
                    acc[i][j] = fmaf(ar[i], br[j], acc[i][j]);
        }
        __syncthreads();
    }

#pragma unroll
    for (int i = 0; i < 4; i++) {
        int m = m0 + tm * 4 + i;
        float bb = bias[m];
        float* dst = C + ((size_t)n * M + m) * L + l0;
        float4 r0 = make_float4(acc[i][0] + bb, acc[i][1] + bb,
                                acc[i][2] + bb, acc[i][3] + bb);
        float4 r1 = make_float4(acc[i][4] + bb, acc[i][5] + bb,
                                acc[i][6] + bb, acc[i][7] + bb);
        *(float4*)(dst + tn * 4) = r0;
        *(float4*)(dst + 64 + tn * 4) = r1;
    }
}

// ============================================================
// Attention partial, key-pair packed.
// grid = 512 (4 n * 8 h * 4 q-tiles(576) * 4 key-segments).
// 288 threads, 2 queries/thread. Smem row per key-pair p (keys 2p,2p+1),
// stride 36 floats (144B): [0..15] K dims interleaved (d0(l),d0(l+1),...),
// [16..31] V dims interleaved, [32..35] pad.
// One FFMA2 = one dim over BOTH keys; V-accumulators keep even/odd-key
// partials packed, folded at the end. Single-pass softmax, no max-sub.
// ============================================================
__global__ void __launch_bounds__(288, 2) attn_part_kernel()
{
    extern __shared__ float kv_s[];   // [288 pairs][36]
    int bid = blockIdx.x;
    int seg = bid & 3;
    int jt  = (bid >> 2) & 3;
    int nh  = bid >> 4;
    int h = nh & 7, n = nh >> 3;
    int t = threadIdx.x;

    const float* base = g_qkv + ((size_t)n * 192 + h * 24) * L;
    int l0 = seg * SEGK;

    // thread t owns key-pair p = t (keys 2t, 2t+1 of this segment)
#pragma unroll
    for (int j = 0; j < 8; j++) {
        float2 kk = *(const float2*)(base + (size_t)(8 + j) * L + l0 + 2 * t);
        float2 vv = *(const float2*)(base + (size_t)(16 + j) * L + l0 + 2 * t);
        *(float2*)&kv_s[t * 36 + 2 * j] = kk;
        *(float2*)&kv_s[t * 36 + 16 + 2 * j] = vv;
    }

    int q0 = jt * 576 + t;
    int q1 = q0 + 288;
    const float QS = 0.35355339059327373f * 1.4426950408889634f; // SCALE*log2(e)

    unsigned long long qA[8], qB[8];
#pragma unroll
    for (int d = 0; d < 8; d++) {
        float a = base[(size_t)d * L + q0] * QS;
        float b = base[(size_t)d * L + q1] * QS;
        PACK64(qA[d], a, a);
        PACK64(qB[d], b, b);
    }

    unsigned long long accA[8], accB[8], ssA2, ssB2;
#pragma unroll
    for (int d = 0; d < 8; d++) { PACK64(accA[d], 0.f, 0.f); PACK64(accB[d], 0.f, 0.f); }
    PACK64(ssA2, 0.f, 0.f); PACK64(ssB2, 0.f, 0.f);

    __syncthreads();

    const ulonglong2* kvu = (const ulonglong2*)kv_s;   // 9 x 16B per pair-row

#pragma unroll 2
    for (int p = 0; p < NPAIR; p++) {
        const ulonglong2* row = kvu + p * 9;
        ulonglong2 k01 = row[0], k23 = row[1], k45 = row[2], k67 = row[3];
        unsigned long long sA, sB;
        MUL2(sA, qA[0], k01.x);
        MUL2(sB, qB[0], k01.x);
        FMA2(sA, qA[1], k01.y, sA);
        FMA2(sB, qB[1], k01.y, sB);
        FMA2(sA, qA[2], k23.x, sA);
        FMA2(sB, qB[2], k23.x, sB);
        FMA2(sA, qA[3], k23.y, sA);
        FMA2(sB, qB[3], k23.y, sB);
        FMA2(sA, qA[4], k45.x, sA);
        FMA2(sB, qB[4], k45.x, sB);
        FMA2(sA, qA[5], k45.y, sA);
        FMA2(sB, qB[5], k45.y, sB);
        FMA2(sA, qA[6], k67.x, sA);
        FMA2(sB, qB[6], k67.x, sB);
        FMA2(sA, qA[7], k67.y, sA);
        FMA2(sB, qB[7], k67.y, sB);

        float a0, a1, b0, b1;
        UNPACK64(a0, a1, sA);
        UNPACK64(b0, b1, sB);
        float eA0, eA1, eB0, eB1;
        asm("ex2.approx.ftz.f32 %0, %1;" : "=f"(eA0) : "f"(a0));
        asm("ex2.approx.ftz.f32 %0, %1;" : "=f"(eA1) : "f"(a1));
        asm("ex2.approx.ftz.f32 %0, %1;" : "=f"(eB0) : "f"(b0));
        asm("ex2.approx.ftz.f32 %0, %1;" : "=f"(eB1) : "f"(b1));
        unsigned long long eA, eB;
        PACK64(eA, eA0, eA1);
        PACK64(eB, eB0, eB1);
        ADD2(ssA2, ssA2, eA);
        ADD2(ssB2, ssB2, eB);

        ulonglong2 v01 = row[4], v23 = row[5], v45 = row[6], v67 = row[7];
        FMA2(accA[0], eA, v01.x, accA[0]);
        FMA2(accB[0], eB, v01.x, accB[0]);
        FMA2(accA[1], eA, v01.y, accA[1]);
        FMA2(accB[1], eB, v01.y, accB[1]);
        FMA2(accA[2], eA, v23.x, accA[2]);
        FMA2(accB[2], eB, v23.x, accB[2]);
        FMA2(accA[3], eA, v23.y, accA[3]);
        FMA2(accB[3], eB, v23.y, accB[3]);
        FMA2(accA[4], eA, v45.x, accA[4]);
        FMA2(accB[4], eB, v45.x, accB[4]);
        FMA2(accA[5], eA, v45.y, accA[5]);
        FMA2(accB[5], eB, v45.y, accB[5]);
        FMA2(accA[6], eA, v67.x, accA[6]);
        FMA2(accB[6], eB, v67.x, accB[6]);
        FMA2(accA[7], eA, v67.y, accA[7]);
        FMA2(accB[7], eB, v67.y, accB[7]);
    }

    int gq0 = nh * L + q0;
    int gq1 = nh * L + q1;
    float x0, x1;
    UNPACK64(x0, x1, ssA2);
    g_psum[seg * NQ + gq0] = x0 + x1;
    UNPACK64(x0, x1, ssB2);
    g_psum[seg * NQ + gq1] = x0 + x1;
#pragma unroll
    for (int d = 0; d < 8; d++) {
        UNPACK64(x0, x1, accA[d]);
        g_pacc[(seg * 8 + d) * NQ + gq0] = x0 + x1;
        UNPACK64(x0, x1, accB[d]);
        g_pacc[(seg * 8 + d) * NQ + gq1] = x0 + x1;
    }
}

// ============================================================
// Combine partials: o[d] = (sum_seg acc)/(sum_seg ssum) -> g_o.
// ============================================================
__global__ void __launch_bounds__(256) attn_combine_kernel()
{
    int gq = blockIdx.x * 256 + threadIdx.x;
    float s = 0.f;
#pragma unroll
    for (int seg = 0; seg < NSEG; seg++) s += g_psum[seg * NQ + gq];
    float inv = 1.0f / s;
    int nh = gq / L;
    int q  = gq - nh * L;
    float* op = g_o + ((size_t)nh * 8) * L + q;
#pragma unroll
    for (int d = 0; d < 8; d++) {
        float o = 0.f;
#pragma unroll
        for (int seg = 0; seg < NSEG; seg++) o += g_pacc[(seg * 8 + d) * NQ + gq];
        op[(size_t)d * L] = o * inv;
    }
}

// ============================================================
// Pos 3x3 conv as implicit GEMM over V, f32x2 + reg double-buffering.
// BM=64 (all oc), BN=64 px, K=576; grid (36,1,4)=144 CTAs, 256 thr.
// Weights stored DUP-PACKED in smem -> inner kk: 3 LDS.128 + 8 FFMA2.
// ============================================================
__global__ void __launch_bounds__(256) pos_gemm_kernel(
    const float* __restrict__ pw, const float* __restrict__ pb)
{
    __shared__ float As2[16][132];   // dup-packed weights: [kk][2*oc{+0,+1}]
    __shared__ float Bs[16][68];
    int n  = blockIdx.z;
    int l0 = blockIdx.x * 64;
    int t  = threadIdx.x;
    int tm = t >> 4, tn = t & 15;

    // B-gather geometry (fixed per thread)
    int col = t & 63;
    int kkb = t >> 6;            // 0..3
    int px = l0 + col;
    int y = px / 48, x = px - y * 48;
    const float* qn = g_qkv + (size_t)n * 192 * L;

    // A-load mapping
    int am = t >> 2;             // oc 0..63
    int ak = (t & 3) * 4;        // kk 0,4,8,12

    // prefetch tile 0 into registers
    float4 aP = *(const float4*)(pw + (size_t)am * 576 + ak);
    float bP[4];
#pragma unroll
    for (int u = 0; u < 4; u++) {
        int k = kkb + u * 4;
        int ic = k / 9, tap = k - ic * 9;
        int tyy = tap / 3;
        int gy = y + tyy - 1, gx = x + (tap - tyy * 3 - 1);
        float v = 0.f;
        if ((unsigned)gy < 48u && (unsigned)gx < 48u) {
            int c = (ic >> 3) * 24 + 16 + (ic & 7);
            v = qn[(size_t)c * L + gy * 48 + gx];
        }
        bP[u] = v;
    }

    unsigned long long acc[4][2];
#pragma unroll
    for (int i = 0; i < 4; i++) { PACK64(acc[i][0], 0.f, 0.f); PACK64(acc[i][1], 0.f, 0.f); }

    for (int k0 = 0; k0 < 576; k0 += 16) {
        // commit prefetched tile to smem
        const float* af = (const float*)&aP;
#pragma unroll
        for (int i = 0; i < 4; i++)
            *(float2*)&As2[ak + i][am * 2] = make_float2(af[i], af[i]);
#pragma unroll
        for (int u = 0; u < 4; u++) Bs[kkb + u * 4][col] = bP[u];
        __syncthreads();

        // prefetch next tile (overlaps with compute below)
        int k1 = k0 + 16;
        if (k1 < 576) {
            aP = *(const float4*)(pw + (size_t)am * 576 + k1 + ak);
#pragma unroll
            for (int u = 0; u < 4; u++) {
                int k = k1 + kkb + u * 4;
                int ic = k / 9, tap = k - ic * 9;
                int tyy = tap / 3;
                int gy = y + tyy - 1, gx = x + (tap - tyy * 3 - 1);
                float v = 0.f;
                if ((unsigned)gy < 48u && (unsigned)gx < 48u) {
                    int c = (ic >> 3) * 24 + 16 + (ic & 7);
                    v = qn[(size_t)c * L + gy * 48 + gx];
                }
                bP[u] = v;
            }
        }

#pragma unroll
        for (int kk = 0; kk < 16; kk++) {
            ulonglong2 a01 = *(const ulonglong2*)&As2[kk][tm * 8];
            ulonglong2 a23 = *(const ulonglong2*)&As2[kk][tm * 8 + 4];
            ulonglong2 b   = *(const ulonglong2*)&Bs[kk][tn * 4];
            FMA2(acc[0][0], a01.x, b.x, acc[0][0]);
            FMA2(acc[0][1], a01.x, b.y, acc[0][1]);
            FMA2(acc[1][0], a01.y, b.x, acc[1][0]);
            FMA2(acc[1][1], a01.y, b.y, acc[1][1]);
            FMA2(acc[2][0], a23.x, b.x, acc[2][0]);
            FMA2(acc[2][1], a23.x, b.y, acc[2][1]);
            FMA2(acc[3][0], a23.y, b.x, acc[3][0]);
            FMA2(acc[3][1], a23.y, b.y, acc[3][1]);
        }
        __syncthreads();
    }

#pragma unroll
    for (int i = 0; i < 4; i++) {
        int oc = tm * 4 + i;
        float bb = pb[oc];
        float* dst = g_o + ((size_t)n * HCH + oc) * L + l0 + tn * 4;
        float o0, o1;
        UNPACK64(o0, o1, acc[i][0]);
        dst[0] += o0 + bb;
        dst[1] += o1 + bb;
        UNPACK64(o0, o1, acc[i][1]);
        dst[2] += o0 + bb;
        dst[3] += o1 + bb;
    }
}

// ============================================================
extern "C" void kernel_launch(void* const* d_in, const int* in_sizes, int n_in,
                              void* d_out, int out_size)
{
    const float* x     = (const float*)d_in[0];
    const float* qkv_w = (const float*)d_in[1];
    const float* qkv_b = (const float*)d_in[2];
    const float* pos_w = (const float*)d_in[3];
    const float* pos_b = (const float*)d_in[4];
    const float* res_w = (const float*)d_in[5];
    const float* res_b = (const float*)d_in[6];
    float* out = (float*)d_out;

    float* qkv_ptr = nullptr;
    float* o_ptr   = nullptr;
    cudaGetSymbolAddress((void**)&qkv_ptr, g_qkv);
    cudaGetSymbolAddress((void**)&o_ptr, g_o);

    // K1: qkv 1x1 conv as GEMM  [192 x 512] * [512 x 2304] per batch
    gemm_bias_kernel<<<dim3(18, 3, NBATCH), 256>>>(qkv_w, x, qkv_b, qkv_ptr, 192, CIN);

    // K2: attention partials (key-pair packed, 2 queries/thread)
    const int ATTN_SMEM = NPAIR * 36 * 4;  // 41472 B
    attn_part_kernel<<<NBATCH * NH * 4 * NSEG, 288, ATTN_SMEM>>>();

    // K3: combine + normalize
    attn_combine_kernel<<<NQ / 256, 256>>>();

    // K4: pos conv as implicit GEMM (f32x2), accumulate into g_o
    pos_gemm_kernel<<<dim3(36, 1, NBATCH), 256>>>(pos_w, pos_b);

    // K5: res 1x1 conv as GEMM  [512 x 64] * [64 x 2304] per batch
    gemm_bias_kernel<<<dim3(18, 8, NBATCH), 256>>>(res_w, o_ptr, res_b, out, 512, HCH);
}

// round 7
// speedup vs baseline: 1.7862x; 1.5210x over previous
#include <cuda_runtime.h>
#include <cuda_fp16.h>
#include <cstdint>

#define L 2304
#define NBATCH 4
#define CIN 512
#define HCH 64
#define NH 8
#define NNH (NBATCH * NH)        // 32
#define NQT 18                   // q tiles of 128
#define NCHUNK 18                // key chunks of 128

// scratch (no cudaMalloc allowed)
__device__ float g_qkv[NBATCH * 192 * L];        // [n][192][L] fp32
__device__ float g_o[NBATCH * HCH * L];          // [n][64][L]
__device__ __half g_qh[NNH * L * 8];             // [nh][q][8]  (scaled)
__device__ __half g_kh[NNH * L * 8];             // [nh][k][8]
__device__ __half g_vh[NNH * 16 * L];            // [nh][dim16][k], plane8=ones

// ---------- packed f32x2 helpers (pos conv) ----------
#define PACK64(r, lo, hi) asm("mov.b64 %0, {%1,%2};" : "=l"(r) : "f"(lo), "f"(hi))
#define UNPACK64(lo, hi, r) asm("mov.b64 {%0,%1}, %2;" : "=f"(lo), "=f"(hi) : "l"(r))
#define FMA2(d, a, b, c) asm("fma.rn.f32x2 %0, %1, %2, %3;" : "=l"(d) : "l"(a), "l"(b), "l"(c))

#define HMMA(c0, c1, c2, c3, a0, a1, a2, a3, b0, b1) \
    asm volatile("mma.sync.aligned.m16n8k16.row.col.f32.f16.f16.f32 " \
        "{%0,%1,%2,%3}, {%4,%5,%6,%7}, {%8,%9}, {%0,%1,%2,%3};" \
        : "+f"(c0), "+f"(c1), "+f"(c2), "+f"(c3) \
        : "r"(a0), "r"(a1), "r"(a2), "r"(a3), "r"(b0), "r"(b1))

// ============================================================
// GEMM with bias (qkv / res 1x1 convs)
// ============================================================
__global__ void __launch_bounds__(256) gemm_bias_kernel(
    const float* __restrict__ A, const float* __restrict__ B,
    const float* __restrict__ bias, float* __restrict__ C,
    int M, int Kdim)
{
    __shared__ float As[16][68];
    __shared__ float Bs[16][132];
    int n  = blockIdx.z;
    int m0 = blockIdx.y * 64;
    int l0 = blockIdx.x * 128;
    int t  = threadIdx.x;
    int tm = t >> 4, tn = t & 15;
    const float* Bn = B + (size_t)n * Kdim * L;

    float acc[4][8];
#pragma unroll
    for (int i = 0; i < 4; i++)
#pragma unroll
        for (int j = 0; j < 8; j++) acc[i][j] = 0.f;

    for (int k0 = 0; k0 < Kdim; k0 += 16) {
        {
            int m = t >> 2, kk = (t & 3) * 4;
            float4 a = *(const float4*)(A + (size_t)(m0 + m) * Kdim + k0 + kk);
            As[kk + 0][m] = a.x; As[kk + 1][m] = a.y;
            As[kk + 2][m] = a.z; As[kk + 3][m] = a.w;
        }
        {
            int kk = t >> 4;
            const float* src = Bn + (size_t)(k0 + kk) * L + l0;
            float4 b0 = *(const float4*)(src + tn * 4);
            float4 b1 = *(const float4*)(src + 64 + tn * 4);
            *(float4*)&Bs[kk][tn * 4] = b0;
            *(float4*)&Bs[kk][64 + tn * 4] = b1;
        }
        __syncthreads();
#pragma unroll
        for (int kk = 0; kk < 16; kk++) {
            float4 a4 = *(const float4*)&As[kk][tm * 4];
            float4 b0 = *(const float4*)&Bs[kk][tn * 4];
            float4 b1 = *(const float4*)&Bs[kk][64 + tn * 4];
            float ar[4] = {a4.x, a4.y, a4.z, a4.w};
            float br[8] = {b0.x, b0.y, b0.z, b0.w, b1.x, b1.y, b1.z, b1.w};
#pragma unroll
            for (int i = 0; i < 4; i++)
#pragma unroll
                for (int j = 0; j < 8; j++)
                    acc[i][j] = fmaf(ar[i], br[j], acc[i][j]);
        }
        __syncthreads();
    }

#pragma unroll
    for (int i = 0; i < 4; i++) {
        int m = m0 + tm * 4 + i;
        float bb = bias[m];
        float* dst = C + ((size_t)n * M + m) * L + l0;
        float4 r0 = make_float4(acc[i][0] + bb, acc[i][1] + bb,
                                acc[i][2] + bb, acc[i][3] + bb);
        float4 r1 = make_float4(acc[i][4] + bb, acc[i][5] + bb,
                                acc[i][6] + bb, acc[i][7] + bb);
        *(float4*)(dst + tn * 4) = r0;
        *(float4*)(dst + 64 + tn * 4) = r1;
    }
}

// ============================================================
// Convert fp32 qkv -> fp16 fragment-friendly images.
//  Q: [nh][q][8] with SCALE*log2e folded; K: [nh][k][8];
//  V: [nh][16 planes][L] (plane 8 = ones, 9..15 = 0).
// ============================================================
#define NT_Q (NNH * L)
#define NT_K (NNH * L)
#define NT_V (NNH * 16 * (L / 8))

__global__ void __launch_bounds__(256) convert_kernel()
{
    const float QS = 0.35355339059327373f * 1.4426950408889634f;
    int id = blockIdx.x * 256 + threadIdx.x;

    if (id < NT_Q) {
        int nh = id / L, q = id - nh * L;
        int n = nh >> 3, h = nh & 7;
        const float* src = g_qkv + ((size_t)n * 192 + h * 24) * L + q;
        uint32_t w[4];
#pragma unroll
        for (int j = 0; j < 4; j++) {
            __half2 h2 = __floats2half2_rn(src[(size_t)(2 * j) * L] * QS,
                                           src[(size_t)(2 * j + 1) * L] * QS);
            w[j] = *(uint32_t*)&h2;
        }
        ((uint4*)g_qh)[id] = make_uint4(w[0], w[1], w[2], w[3]);
        return;
    }
    id -= NT_Q;
    if (id < NT_K) {
        int nh = id / L, k = id - nh * L;
        int n = nh >> 3, h = nh & 7;
        const float* src = g_qkv + ((size_t)n * 192 + h * 24 + 8) * L + k;
        uint32_t w[4];
#pragma unroll
        for (int j = 0; j < 4; j++) {
            __half2 h2 = __floats2half2_rn(src[(size_t)(2 * j) * L],
                                           src[(size_t)(2 * j + 1) * L]);
            w[j] = *(uint32_t*)&h2;
        }
        ((uint4*)g_kh)[id] = make_uint4(w[0], w[1], w[2], w[3]);
        return;
    }
    id -= NT_K;
    if (id < NT_V) {
        int nh = id / (16 * (L / 8));
        int rem = id - nh * 16 * (L / 8);
        int dim = rem / (L / 8);
        int blk = rem - dim * (L / 8);
        uint4 out;
        if (dim < 8) {
            int n = nh >> 3, h = nh & 7;
            const float* src = g_qkv + ((size_t)n * 192 + h * 24 + 16 + dim) * L + blk * 8;
            float4 f0 = *(const float4*)src;
            float4 f1 = *(const float4*)(src + 4);
            __half2 a = __floats2half2_rn(f0.x, f0.y);
            __half2 b = __floats2half2_rn(f0.z, f0.w);
            __half2 c = __floats2half2_rn(f1.x, f1.y);
            __half2 d = __floats2half2_rn(f1.z, f1.w);
            out = make_uint4(*(uint32_t*)&a, *(uint32_t*)&b, *(uint32_t*)&c, *(uint32_t*)&d);
        } else if (dim == 8) {
            out = make_uint4(0x3C003C00u, 0x3C003C00u, 0x3C003C00u, 0x3C003C00u);
        } else {
            out = make_uint4(0, 0, 0, 0);
        }
        ((uint4*)g_vh)[(size_t)(nh * 16 + dim) * (L / 8) + blk] = out;
    }
}

// ============================================================
// Attention via HMMA m16n8k16 (f16 in, f32 accum).
// grid = 576 (nh * 18 q-tiles), 256 threads = 8 warps x 16 q-rows.
// S-MMA uses padding dim 8 to compute (S - 9) for free (Q pad = -9,
// K pad = 1): keeps e^S within f16 range; ratio o/ssum is invariant.
// Residual tail clamped at s<=15. V plane 8 = ones => ssum in fp32.
// ============================================================
__global__ void __launch_bounds__(256) attn_hmma_kernel()
{
    __shared__ uint32_t sK[2][512];        // [buf][key*4 + dimpair]
    __shared__ uint32_t sV[2][16 * 68];    // [buf][plane*68 + keyword]
    int t = threadIdx.x, wid = t >> 5, lane = t & 31;
    int bid = blockIdx.x;
    int qt = bid % NQT;
    int nh = bid / NQT;
    int r = lane >> 2, cq = lane & 3;

    const uint32_t* kg = (const uint32_t*)g_kh + (size_t)nh * L * 4;
    const uint32_t* vg = (const uint32_t*)g_vh + (size_t)nh * 16 * (L / 2);

    // Q fragments (constant over chunks)
    int q0 = qt * 128 + wid * 16;
    const uint32_t* qgp = (const uint32_t*)g_qh + (size_t)(nh * L + q0) * 4;
    uint32_t qa0 = qgp[r * 4 + cq];
    uint32_t qa1 = qgp[(r + 8) * 4 + cq];
    // shift trick: A[row][dim8] = -9 (half 0xC880), B[dim8][n] = 1 (0x3C00)
    uint32_t qa2 = (cq == 0) ? 0x0000C880u : 0u;   // k=8 slot, rows r / r+8
    uint32_t kb1 = (cq == 0) ? 0x00003C00u : 0u;

    int pl = t >> 4, qw = t & 15;

    // preload chunk 0
    uint2 kreg = ((const uint2*)kg)[t];
    uint4 vreg = *(const uint4*)(vg + (size_t)pl * (L / 2) + qw * 4);
    ((uint2*)sK[0])[t] = kreg;
    *(uint4*)&sV[0][pl * 68 + qw * 4] = vreg;
    __syncthreads();

    float o0[4] = {0.f, 0.f, 0.f, 0.f};
    float o1[4] = {0.f, 0.f, 0.f, 0.f};

    for (int c = 0; c < NCHUNK; c++) {
        int cur = c & 1;
        if (c + 1 < NCHUNK) {   // register-staged prefetch
            kreg = ((const uint2*)(kg + (size_t)(c + 1) * 512))[t];
            vreg = *(const uint4*)(vg + (size_t)pl * (L / 2) + (c + 1) * 64 + qw * 4);
        }

        uint32_t pa[16], pb[16];
#pragma unroll
        for (int j = 0; j < 16; j++) {
            uint32_t kb = sK[cur][j * 32 + r * 4 + cq];
            float s0 = 0.f, s1 = 0.f, s2 = 0.f, s3 = 0.f;
            HMMA(s0, s1, s2, s3, qa0, qa1, qa2, qa2, kb, kb1);
            s0 = fminf(s0, 15.f); s1 = fminf(s1, 15.f);
            s2 = fminf(s2, 15.f); s3 = fminf(s3, 15.f);
            uint32_t x, y;
            asm("cvt.rn.f16x2.f32 %0, %1, %2;" : "=r"(x) : "f"(s1), "f"(s0));
            asm("ex2.approx.f16x2 %0, %1;" : "=r"(x) : "r"(x));
            asm("cvt.rn.f16x2.f32 %0, %1, %2;" : "=r"(y) : "f"(s3), "f"(s2));
            asm("ex2.approx.f16x2 %0, %1;" : "=r"(y) : "r"(y));
            pa[j] = x;
            pb[j] = y;
        }

#pragma unroll
        for (int s = 0; s < 8; s++) {
            uint32_t b0 = sV[cur][r * 68 + s * 8 + cq];
            uint32_t b1 = sV[cur][r * 68 + s * 8 + cq + 4];
            HMMA(o0[0], o0[1], o0[2], o0[3],
                 pa[2 * s], pb[2 * s], pa[2 * s + 1], pb[2 * s + 1], b0, b1);
            uint32_t b2 = sV[cur][(r + 8) * 68 + s * 8 + cq];
            uint32_t b3 = sV[cur][(r + 8) * 68 + s * 8 + cq + 4];
            HMMA(o1[0], o1[1], o1[2], o1[3],
                 pa[2 * s], pb[2 * s], pa[2 * s + 1], pb[2 * s + 1], b2, b3);
        }

        if (c + 1 < NCHUNK) {
            int nxt = cur ^ 1;
            ((uint2*)sK[nxt])[t] = kreg;
            *(uint4*)&sV[nxt][pl * 68 + qw * 4] = vreg;
        }
        __syncthreads();
    }

    // ssum lives in dim-8 column: o1[0]/o1[2] of lanes with cq==0
    float ss_lo = __shfl_sync(0xffffffffu, o1[0], lane & ~3);
    float ss_hi = __shfl_sync(0xffffffffu, o1[2], lane & ~3);
    float inv_lo = 1.f / fmaxf(ss_lo, 1e-30f);
    float inv_hi = 1.f / fmaxf(ss_hi, 1e-30f);

    int n = nh >> 3, h = nh & 7;
    float* dst = g_o + ((size_t)n * HCH + h * 8 + cq * 2) * L + q0 + r;
    dst[0]     = o0[0] * inv_lo;
    dst[8]     = o0[2] * inv_hi;
    dst[L]     = o0[1] * inv_lo;
    dst[L + 8] = o0[3] * inv_hi;
}

// ============================================================
// Pos 3x3 conv as implicit GEMM over V (f32x2, prefetch, BN=32).
// grid (72,1,4) = 288 CTAs.
// ============================================================
__global__ void __launch_bounds__(256) pos_gemm_kernel(
    const float* __restrict__ pw, const float* __restrict__ pb)
{
    __shared__ float As2[16][132];   // dup-packed weights
    __shared__ float Bs[16][36];
    int n  = blockIdx.z;
    int l0 = blockIdx.x * 32;
    int t  = threadIdx.x;
    int tm = t >> 4, tn = t & 15;

    int col = t & 31;
    int kkb = t >> 5;            // 0..7 -> kk = kkb, kkb+8
    int px = l0 + col;
    int y = px / 48, x = px - y * 48;
    const float* qn = g_qkv + (size_t)n * 192 * L;

    int am = t >> 2;
    int ak = (t & 3) * 4;

    float4 aP = *(const float4*)(pw + (size_t)am * 576 + ak);
    float bP[2];
#pragma unroll
    for (int u = 0; u < 2; u++) {
        int k = kkb + u * 8;
        int ic = k / 9, tap = k - ic * 9;
        int tyy = tap / 3;
        int gy = y + tyy - 1, gx = x + (tap - tyy * 3 - 1);
        float v = 0.f;
        if ((unsigned)gy < 48u && (unsigned)gx < 48u) {
            int ch = (ic >> 3) * 24 + 16 + (ic & 7);
            v = qn[(size_t)ch * L + gy * 48 + gx];
        }
        bP[u] = v;
    }

    unsigned long long acc[4];
#pragma unroll
    for (int i = 0; i < 4; i++) PACK64(acc[i], 0.f, 0.f);

    for (int k0 = 0; k0 < 576; k0 += 16) {
        const float* af = (const float*)&aP;
#pragma unroll
        for (int i = 0; i < 4; i++)
            *(float2*)&As2[ak + i][am * 2] = make_float2(af[i], af[i]);
        Bs[kkb][col] = bP[0];
        Bs[kkb + 8][col] = bP[1];
        __syncthreads();

        int k1 = k0 + 16;
        if (k1 < 576) {
            aP = *(const float4*)(pw + (size_t)am * 576 + k1 + ak);
#pragma unroll
            for (int u = 0; u < 2; u++) {
                int k = k1 + kkb + u * 8;
                int ic = k / 9, tap = k - ic * 9;
                int tyy = tap / 3;
                int gy = y + tyy - 1, gx = x + (tap - tyy * 3 - 1);
                float v = 0.f;
                if ((unsigned)gy < 48u && (unsigned)gx < 48u) {
                    int ch = (ic >> 3) * 24 + 16 + (ic & 7);
                    v = qn[(size_t)ch * L + gy * 48 + gx];
                }
                bP[u] = v;
            }
        }

#pragma unroll
        for (int kk = 0; kk < 16; kk++) {
            ulonglong2 a01 = *(const ulonglong2*)&As2[kk][tm * 8];
            ulonglong2 a23 = *(const ulonglong2*)&As2[kk][tm * 8 + 4];
            unsigned long long b = *(const unsigned long long*)&Bs[kk][tn * 2];
            FMA2(acc[0], a01.x, b, acc[0]);
            FMA2(acc[1], a01.y, b, acc[1]);
            FMA2(acc[2], a23.x, b, acc[2]);
            FMA2(acc[3], a23.y, b, acc[3]);
        }
        __syncthreads();
    }

#pragma unroll
    for (int i = 0; i < 4; i++) {
        int oc = tm * 4 + i;
        float bb = pb[oc];
        float* dst = g_o + ((size_t)n * HCH + oc) * L + l0 + tn * 2;
        float o0, o1;
        UNPACK64(o0, o1, acc[i]);
        dst[0] += o0 + bb;
        dst[1] += o1 + bb;
    }
}

// ============================================================
extern "C" void kernel_launch(void* const* d_in, const int* in_sizes, int n_in,
                              void* d_out, int out_size)
{
    const float* x     = (const float*)d_in[0];
    const float* qkv_w = (const float*)d_in[1];
    const float* qkv_b = (const float*)d_in[2];
    const float* pos_w = (const float*)d_in[3];
    const float* pos_b = (const float*)d_in[4];
    const float* res_w = (const float*)d_in[5];
    const float* res_b = (const float*)d_in[6];
    float* out = (float*)d_out;

    float* qkv_ptr = nullptr;
    float* o_ptr   = nullptr;
    cudaGetSymbolAddress((void**)&qkv_ptr, g_qkv);
    cudaGetSymbolAddress((void**)&o_ptr, g_o);

    // K1: qkv 1x1 conv as GEMM
    gemm_bias_kernel<<<dim3(18, 3, NBATCH), 256>>>(qkv_w, x, qkv_b, qkv_ptr, 192, CIN);

    // K2: fp32 -> fp16 fragment images
    {
        int total = NT_Q + NT_K + NT_V;
        convert_kernel<<<(total + 255) / 256, 256>>>();
    }

    // K3: attention (HMMA tensor cores)
    attn_hmma_kernel<<<NNH * NQT, 256>>>();

    // K4: pos conv, accumulate into g_o
    pos_gemm_kernel<<<dim3(72, 1, NBATCH), 256>>>(pos_w, pos_b);

    // K5: res 1x1 conv as GEMM
    gemm_bias_kernel<<<dim3(18, 8, NBATCH), 256>>>(res_w, o_ptr, res_b, out, 512, HCH);
}